// round 11
// baseline (speedup 1.0000x reference)
#include <cuda_runtime.h>
#include <cstdint>
#include <math_constants.h>

#define DCOLS 2048
#define THREADS 256
#define CAP 384
#define WWIN 1.75f   // pass-1 candidate window width below rawmax

__device__ float michelot_row_global(const float* xr, const int* mr) {
    // Fallback (statistically unreachable): Michelot over full row from global.
    float S = 0.f; int k = 0;
    for (int i = 0; i < DCOLS; i++) if (__ldg(&mr[i])) { S += __ldg(&xr[i]); k++; }
    if (k == 0) return CUDART_INF_F;
    float tau = (S - 1.0f) / (float)k;
    int prevc = k;
    for (int it = 0; it < DCOLS + 2; it++) {
        float s = 0.f; int cc = 0;
        for (int i = 0; i < DCOLS; i++) {
            if (__ldg(&mr[i])) { float z = __ldg(&xr[i]); if (z > tau) { s += z; cc++; } }
        }
        if (cc == prevc || cc == 0) break;
        tau = (s - 1.0f) / (float)cc;
        prevc = cc;
    }
    return tau;
}

// Exact Michelot starting from threshold tau0; initial working set {c[i] > tau0}
// must contain the support. -inf entries are excluded automatically.
__device__ __forceinline__ float michelot_tau0(const float* c, int k, float tau0) {
    float tau = tau0;
    int prevc = -1;
    for (int it = 0; it < CAP + 2; it++) {
        float s = 0.f; int cc = 0;
        for (int i = 0; i < k; i++) {
            float z = c[i];
            if (z > tau) { s += z; cc++; }
        }
        if (cc == prevc || cc == 0) break;
        tau = (s - 1.0f) / (float)cc;
        prevc = cc;
    }
    return tau;
}

__global__ __launch_bounds__(THREADS, 8) void sparsemax_kernel(
    const float* __restrict__ x,
    const int* __restrict__ mask,
    float* __restrict__ out)
{
    const int row = blockIdx.x;
    const int t = threadIdx.x;
    const int warp = t >> 5, lane = t & 31;

    const float4* xr = reinterpret_cast<const float4*>(x + (size_t)row * DCOLS);
    const int*  mrow = mask + (size_t)row * DCOLS;
    float4* orow = reinterpret_cast<float4*>(out + (size_t)row * DCOLS);

    __shared__ float s_wmax[8];
    __shared__ int   s_cnt;
    __shared__ float s_tau;
    __shared__ int   s_flag;
    __shared__ float s_cand[CAP];

    // Load x only (8 elements / thread). Mask is fetched lazily below.
    float4 v0 = xr[t];
    float4 v1 = xr[t + THREADS];
    float vals[8] = {v0.x, v0.y, v0.z, v0.w, v1.x, v1.y, v1.z, v1.w};

    bool have_mask = false;   // pass 1: raw x; pass 2: vals folded with full mask

    #pragma unroll 1
    for (int pass = 0; pass < 2; pass++) {
        // ---- block max of current vals ----
        float mx = vals[0];
        #pragma unroll
        for (int i = 1; i < 8; i++) mx = fmaxf(mx, vals[i]);
        #pragma unroll
        for (int o = 16; o; o >>= 1)
            mx = fmaxf(mx, __shfl_xor_sync(0xFFFFFFFFu, mx, o));
        if (lane == 0) s_wmax[warp] = mx;
        if (t == 0) s_cnt = 0;
        __syncthreads();                                   // sync A
        float bmax = s_wmax[0];
        #pragma unroll
        for (int i = 1; i < 8; i++) bmax = fmaxf(bmax, s_wmax[i]);

        // pass 1: wide window below rawmax; pass 2: exact activemax - 1 window
        const float th = bmax - (have_mask ? 1.0f : WWIN);

        // ---- warp-aggregated compaction; lazy per-candidate mask fetch ----
        #pragma unroll
        for (int i = 0; i < 8; i++) {
            const bool p = vals[i] > th;
            const unsigned b = __ballot_sync(0xFFFFFFFFu, p);
            if (b) {
                const int leader = __ffs(b) - 1;
                int base = 0;
                if (lane == leader) base = atomicAdd(&s_cnt, __popc(b));
                base = __shfl_sync(0xFFFFFFFFu, base, leader);
                if (p) {
                    float v = vals[i];
                    if (!have_mask) {
                        const int flat = (i < 4) ? (t * 4 + i)
                                                 : (1024 + t * 4 + (i - 4));
                        if (mrow[flat] == 0) { v = -CUDART_INF_F; vals[i] = v; }
                    }
                    const int idx = base + __popc(b & ((1u << lane) - 1u));
                    if (idx < CAP) s_cand[idx] = v;
                }
            }
        }
        __syncthreads();                                   // sync B

        // ---- solver thread ----
        if (t == 0) {
            const int k = s_cnt;
            const int kk = (k < CAP) ? k : CAP;
            float am = -CUDART_INF_F;                      // active candidate max
            for (int i = 0; i < kk; i++) am = fmaxf(am, s_cand[i]);
            if (!have_mask) {
                // Window valid iff th <= am - 1, i.e. am >= bmax - (WWIN - 1).
                const bool valid = (k <= CAP) && (am >= bmax - (WWIN - 1.0f));
                if (valid) { s_tau = michelot_tau0(s_cand, k, am - 1.0f); s_flag = 0; }
                else       { s_flag = 1; }
            } else {
                float tau;
                if (k == 0)        tau = CUDART_INF_F;     // all-masked row
                else if (k <= CAP) tau = michelot_tau0(s_cand, k, am - 1.0f);
                else               tau = michelot_row_global(x + (size_t)row * DCOLS, mrow);
                s_tau = tau; s_flag = 0;
            }
        }
        __syncthreads();                                   // sync C
        if (s_flag == 0) break;

        // ---- rare fallback: load full mask row, fold, retry exactly (R6 path) ----
        const int4* mr4 = reinterpret_cast<const int4*>(mrow);
        int4 m0 = mr4[t];
        int4 m1 = mr4[t + THREADS];
        if (!m0.x) vals[0] = -CUDART_INF_F;
        if (!m0.y) vals[1] = -CUDART_INF_F;
        if (!m0.z) vals[2] = -CUDART_INF_F;
        if (!m0.w) vals[3] = -CUDART_INF_F;
        if (!m1.x) vals[4] = -CUDART_INF_F;
        if (!m1.y) vals[5] = -CUDART_INF_F;
        if (!m1.z) vals[6] = -CUDART_INF_F;
        if (!m1.w) vals[7] = -CUDART_INF_F;
        have_mask = true;
    }
    const float tau = s_tau;

    // ---- output: relu(v - tau). Masked candidates are -inf -> 0; every other
    //      element (candidate-window excluded) satisfies v <= th <= tau -> 0. ----
    float4 o0, o1;
    o0.x = fmaxf(vals[0] - tau, 0.f);
    o0.y = fmaxf(vals[1] - tau, 0.f);
    o0.z = fmaxf(vals[2] - tau, 0.f);
    o0.w = fmaxf(vals[3] - tau, 0.f);
    o1.x = fmaxf(vals[4] - tau, 0.f);
    o1.y = fmaxf(vals[5] - tau, 0.f);
    o1.z = fmaxf(vals[6] - tau, 0.f);
    o1.w = fmaxf(vals[7] - tau, 0.f);
    orow[t] = o0;
    orow[t + THREADS] = o1;
}

extern "C" void kernel_launch(void* const* d_in, const int* in_sizes, int n_in,
                              void* d_out, int out_size) {
    const float* x = (const float*)d_in[0];
    const int* mask = (const int*)d_in[1];
    float* out = (float*)d_out;

    const int rows = out_size / DCOLS;   // 16384
    sparsemax_kernel<<<rows, THREADS>>>(x, mask, out);
}

// round 12
// speedup vs baseline: 3.4953x; 3.4953x over previous
#include <cuda_runtime.h>
#include <cstdint>
#include <math_constants.h>

#define DCOLS 2048
#define THREADS 256
#define CAP 256
#define GRID 1184   // 148 SMs x 8 resident CTAs: exactly one wave, zero transitions

__device__ __forceinline__ float michelot_list(const float* c, int k) {
    // Exact sparsemax threshold over candidate list c[0..k) (scalar, R6-proven).
    float S = 0.f;
    for (int i = 0; i < k; i++) S += c[i];
    float tau = (S - 1.0f) / (float)k;
    int prevc = k;
    for (int it = 0; it < CAP + 2; it++) {
        float s = 0.f; int cc = 0;
        for (int i = 0; i < k; i++) {
            float z = c[i];
            if (z > tau) { s += z; cc++; }
        }
        if (cc == prevc || cc == 0) break;
        tau = (s - 1.0f) / (float)cc;
        prevc = cc;
    }
    return tau;
}

__device__ float michelot_row_global(const float* xr, const int* mr) {
    // Fallback (statistically unreachable): Michelot over full row from global.
    float S = 0.f; int k = 0;
    for (int i = 0; i < DCOLS; i++) if (__ldg(&mr[i])) { S += __ldg(&xr[i]); k++; }
    if (k == 0) return CUDART_INF_F;
    float tau = (S - 1.0f) / (float)k;
    int prevc = k;
    for (int it = 0; it < DCOLS + 2; it++) {
        float s = 0.f; int cc = 0;
        for (int i = 0; i < DCOLS; i++) {
            if (__ldg(&mr[i])) { float z = __ldg(&xr[i]); if (z > tau) { s += z; cc++; } }
        }
        if (cc == prevc || cc == 0) break;
        tau = (s - 1.0f) / (float)cc;
        prevc = cc;
    }
    return tau;
}

__global__ __launch_bounds__(THREADS, 8) void sparsemax_kernel(
    const float* __restrict__ x,
    const int* __restrict__ mask,
    float* __restrict__ out,
    int rows)
{
    const int t = threadIdx.x;
    const int warp = t >> 5, lane = t & 31;

    __shared__ float s_wmax[8];
    __shared__ int   s_cnt;
    __shared__ float s_tau;
    __shared__ float s_cand[CAP];

    // Grid-stride over rows: body identical to the R6 winner.
    for (int row = blockIdx.x; row < rows; row += GRID) {
        const float4* xr = reinterpret_cast<const float4*>(x + (size_t)row * DCOLS);
        const int4*   mr = reinterpret_cast<const int4*>(mask + (size_t)row * DCOLS);
        float4* orow = reinterpret_cast<float4*>(out + (size_t)row * DCOLS);

        // Load 8 values + 8 mask words, fold mask immediately: inactive -> -inf.
        float4 v0 = xr[t];
        float4 v1 = xr[t + THREADS];
        int4 m0 = mr[t];
        int4 m1 = mr[t + THREADS];

        float vals[8];
        vals[0] = m0.x ? v0.x : -CUDART_INF_F;
        vals[1] = m0.y ? v0.y : -CUDART_INF_F;
        vals[2] = m0.z ? v0.z : -CUDART_INF_F;
        vals[3] = m0.w ? v0.w : -CUDART_INF_F;
        vals[4] = m1.x ? v1.x : -CUDART_INF_F;
        vals[5] = m1.y ? v1.y : -CUDART_INF_F;
        vals[6] = m1.z ? v1.z : -CUDART_INF_F;
        vals[7] = m1.w ? v1.w : -CUDART_INF_F;

        // ---- Phase 1: block max ----
        float mx = vals[0];
        #pragma unroll
        for (int i = 1; i < 8; i++) mx = fmaxf(mx, vals[i]);
        #pragma unroll
        for (int o = 16; o; o >>= 1)
            mx = fmaxf(mx, __shfl_xor_sync(0xFFFFFFFFu, mx, o));
        if (lane == 0) s_wmax[warp] = mx;
        if (t == 0) s_cnt = 0;
        __syncthreads();                                   // sync A
        float allmax = s_wmax[0];
        #pragma unroll
        for (int i = 1; i < 8; i++) allmax = fmaxf(allmax, s_wmax[i]);

        // ---- Phase 2: warp-aggregated compaction of {v > max-1} ----
        // (all-inactive row: allmax=-inf, -inf > -inf is false -> k stays 0)
        const float thresh = allmax - 1.0f;
        #pragma unroll
        for (int i = 0; i < 8; i++) {
            const bool p = vals[i] > thresh;
            const unsigned b = __ballot_sync(0xFFFFFFFFu, p);
            if (b) {
                const int leader = __ffs(b) - 1;
                int base = 0;
                if (lane == leader) base = atomicAdd(&s_cnt, __popc(b));
                base = __shfl_sync(0xFFFFFFFFu, base, leader);
                if (p) {
                    int idx = base + __popc(b & ((1u << lane) - 1u));
                    if (idx < CAP) s_cand[idx] = vals[i];
                }
            }
        }
        __syncthreads();                                   // sync B
        const int k = s_cnt;

        // ---- Phase 3: single solver thread (scalar, R6-proven) ----
        if (t == 0) {
            float tau;
            if (k == 0)        tau = CUDART_INF_F;         // all-zero row
            else if (k <= CAP) tau = michelot_list(s_cand, k);
            else               tau = michelot_row_global(x + (size_t)row * DCOLS,
                                                         mask + (size_t)row * DCOLS);
            s_tau = tau;
        }
        __syncthreads();                                   // sync C
        const float tau = s_tau;

        // ---- Phase 4: p = relu(v - tau); -inf entries give 0 automatically ----
        float4 o0, o1;
        o0.x = fmaxf(vals[0] - tau, 0.f);
        o0.y = fmaxf(vals[1] - tau, 0.f);
        o0.z = fmaxf(vals[2] - tau, 0.f);
        o0.w = fmaxf(vals[3] - tau, 0.f);
        o1.x = fmaxf(vals[4] - tau, 0.f);
        o1.y = fmaxf(vals[5] - tau, 0.f);
        o1.z = fmaxf(vals[6] - tau, 0.f);
        o1.w = fmaxf(vals[7] - tau, 0.f);
        orow[t] = o0;
        orow[t + THREADS] = o1;

        __syncthreads();   // protect s_cnt/s_cand reuse across loop iterations
    }
}

extern "C" void kernel_launch(void* const* d_in, const int* in_sizes, int n_in,
                              void* d_out, int out_size) {
    const float* x = (const float*)d_in[0];
    const int* mask = (const int*)d_in[1];
    float* out = (float*)d_out;

    const int rows = out_size / DCOLS;   // 16384
    sparsemax_kernel<<<GRID, THREADS>>>(x, mask, out, rows);
}

// round 13
// speedup vs baseline: 3.9306x; 1.1246x over previous
#include <cuda_runtime.h>
#include <cstdint>
#include <math_constants.h>

#define DCOLS 2048
#define THREADS 256
#define CAP 256

__device__ __forceinline__ float michelot_list(const float* c, int k) {
    // Exact sparsemax threshold over candidate list c[0..k) (all finite, > max-1).
    float S = 0.f;
    for (int i = 0; i < k; i++) S += c[i];
    float tau = (S - 1.0f) / (float)k;
    int prevc = k;
    for (int it = 0; it < CAP + 2; it++) {
        float s = 0.f; int cc = 0;
        for (int i = 0; i < k; i++) {
            float z = c[i];
            if (z > tau) { s += z; cc++; }
        }
        if (cc == prevc || cc == 0) break;
        tau = (s - 1.0f) / (float)cc;
        prevc = cc;
    }
    return tau;
}

__device__ float michelot_row_global(const float* xr, const int* mr) {
    // Fallback (statistically unreachable): serial Michelot over full row.
    float S = 0.f; int k = 0;
    for (int i = 0; i < DCOLS; i++) if (mr[i]) { S += xr[i]; k++; }
    float tau = (S - 1.0f) / (float)k;
    int prevc = k;
    for (int it = 0; it < DCOLS + 2; it++) {
        float s = 0.f; int cc = 0;
        for (int i = 0; i < DCOLS; i++) {
            if (mr[i]) { float z = xr[i]; if (z > tau) { s += z; cc++; } }
        }
        if (cc == prevc || cc == 0) break;
        tau = (s - 1.0f) / (float)cc;
        prevc = cc;
    }
    return tau;
}

__global__ __launch_bounds__(THREADS, 8) void sparsemax_kernel(
    const float* __restrict__ x,
    const int* __restrict__ mask,
    float* __restrict__ out)
{
    const int row = blockIdx.x;
    const int t = threadIdx.x;
    const int warp = t >> 5, lane = t & 31;

    const float4* xr = reinterpret_cast<const float4*>(x + (size_t)row * DCOLS);
    const int4*   mr = reinterpret_cast<const int4*>(mask + (size_t)row * DCOLS);
    float4* orow = reinterpret_cast<float4*>(out + (size_t)row * DCOLS);

    __shared__ float s_wmax[8];
    __shared__ int   s_cnt;
    __shared__ float s_tau;
    __shared__ float s_cand[CAP];

    // Load 8 values + 8 mask words, fold mask immediately: inactive -> -inf.
    float4 v0 = xr[t];
    float4 v1 = xr[t + THREADS];
    int4 m0 = mr[t];
    int4 m1 = mr[t + THREADS];

    float vals[8];
    vals[0] = m0.x ? v0.x : -CUDART_INF_F;
    vals[1] = m0.y ? v0.y : -CUDART_INF_F;
    vals[2] = m0.z ? v0.z : -CUDART_INF_F;
    vals[3] = m0.w ? v0.w : -CUDART_INF_F;
    vals[4] = m1.x ? v1.x : -CUDART_INF_F;
    vals[5] = m1.y ? v1.y : -CUDART_INF_F;
    vals[6] = m1.z ? v1.z : -CUDART_INF_F;
    vals[7] = m1.w ? v1.w : -CUDART_INF_F;

    // ---- Phase 1: block max (max alone decides: max is always a candidate) ----
    float mx = vals[0];
    #pragma unroll
    for (int i = 1; i < 8; i++) mx = fmaxf(mx, vals[i]);
    #pragma unroll
    for (int o = 16; o; o >>= 1)
        mx = fmaxf(mx, __shfl_xor_sync(0xFFFFFFFFu, mx, o));
    if (lane == 0) s_wmax[warp] = mx;
    if (t == 0) s_cnt = 0;
    __syncthreads();
    float allmax = s_wmax[0];
    #pragma unroll
    for (int i = 1; i < 8; i++) allmax = fmaxf(allmax, s_wmax[i]);

    // ---- Phase 2: warp-aggregated compaction of {v > max-1} ----
    // (if row is all-inactive: allmax=-inf, thresh=-inf, -inf > -inf false -> k=0)
    const float thresh = allmax - 1.0f;
    #pragma unroll
    for (int i = 0; i < 8; i++) {
        const bool p = vals[i] > thresh;
        const unsigned b = __ballot_sync(0xFFFFFFFFu, p);
        if (b) {
            const int leader = __ffs(b) - 1;
            int base = 0;
            if (lane == leader) base = atomicAdd(&s_cnt, __popc(b));
            base = __shfl_sync(0xFFFFFFFFu, base, leader);
            if (p) {
                int idx = base + __popc(b & ((1u << lane) - 1u));
                if (idx < CAP) s_cand[idx] = vals[i];
            }
        }
    }
    __syncthreads();
    const int k = s_cnt;

    // ---- Phase 3: exact threshold (serial, tiny candidate set) ----
    if (t == 0) {
        float tau;
        if (k == 0)        tau = CUDART_INF_F;            // all-inactive row -> zeros
        else if (k <= CAP) tau = michelot_list(s_cand, k);
        else               tau = michelot_row_global(x + (size_t)row * DCOLS,
                                                     mask + (size_t)row * DCOLS);
        s_tau = tau;
    }
    __syncthreads();
    const float tau = s_tau;

    // ---- Phase 4: p = relu(v - tau); -inf entries give 0 automatically ----
    float4 o0, o1;
    o0.x = fmaxf(vals[0] - tau, 0.f);
    o0.y = fmaxf(vals[1] - tau, 0.f);
    o0.z = fmaxf(vals[2] - tau, 0.f);
    o0.w = fmaxf(vals[3] - tau, 0.f);
    o1.x = fmaxf(vals[4] - tau, 0.f);
    o1.y = fmaxf(vals[5] - tau, 0.f);
    o1.z = fmaxf(vals[6] - tau, 0.f);
    o1.w = fmaxf(vals[7] - tau, 0.f);
    orow[t] = o0;
    orow[t + THREADS] = o1;
}

extern "C" void kernel_launch(void* const* d_in, const int* in_sizes, int n_in,
                              void* d_out, int out_size) {
    const float* x = (const float*)d_in[0];
    const int* mask = (const int*)d_in[1];
    float* out = (float*)d_out;

    const int rows = out_size / DCOLS;   // 16384
    sparsemax_kernel<<<rows, THREADS>>>(x, mask, out);
}